// round 7
// baseline (speedup 1.0000x reference)
#include <cuda_runtime.h>
#include <cuda_bf16.h>

// Problem constants
#define S_TOK 8192
#define D_DIM 2048
#define E_EXP 64
#define CAP   128
#define SEC   (S_TOK * E_EXP * CAP)   // 67108864
#define LAST_F 134217728              // tail float index; out_size = LAST_F+1
#define N4_ALL 33554432               // float4 covering floats [0, LAST_F)
#define ZPB    (N4_ALL / 128)         // float4 zeroed per gate block = 262144

// -------------------- device scratch --------------------
__device__ float g_gate[S_TOK];
__device__ int   g_expert[S_TOK];
__device__ float g_me_part[(S_TOK / 64) * E_EXP];  // [128][64] per-block col sums
__device__ float g_vals[E_EXP];                    // me_e * cnt_e

// -------------------- packed fp32 FMA (FFMA2) --------------------
__device__ __forceinline__ void ffma2(float2& d, const float2& a, const float2& b) {
    unsigned long long dd = *(const unsigned long long*)&d;
    unsigned long long aa = *(const unsigned long long*)&a;
    unsigned long long bb = *(const unsigned long long*)&b;
    asm("fma.rn.f32x2 %0, %1, %2, %0;" : "+l"(dd) : "l"(aa), "l"(bb));
    d = *(float2*)&dd;
}

// -------------------- fused GEMM + softmax/argmax + bulk zero ----------------
// BM=64 tokens/block, BN=64 experts, BK=32. 256 threads = 16x16.
// Each block also zeroes ZPB float4 (4MB) of the output, interleaved into the
// compute loop (2 STG.128 per kk8 step) so DRAM writes overlap FMA issue.
#define ASTRIDE 36
__global__ __launch_bounds__(256) void k_gatezero(const float* __restrict__ x,
                                                  const float* __restrict__ wg,
                                                  float4* __restrict__ out4) {
    __shared__ float sm[2 * 64 * ASTRIDE];   // 4608 floats; reused as logits
    __shared__ float smax[64], sinv[64];
    float* sA = sm;
    float* sB = sm + 64 * ASTRIDE;

    const int tid = threadIdx.x;
    const int tx = tid & 15, ty = tid >> 4;
    const int m0 = blockIdx.x * 64;
    const float4 z4 = make_float4(0.f, 0.f, 0.f, 0.f);
    const size_t zblock = (size_t)blockIdx.x * ZPB;

    float2 acc[4][4];
#pragma unroll
    for (int i = 0; i < 4; i++)
#pragma unroll
        for (int j = 0; j < 4; j++) acc[i][j] = make_float2(0.f, 0.f);

    for (int it = 0; it < D_DIM / 32; it++) {
        const int k0 = it * 32;
        __syncthreads();
#pragma unroll
        for (int r = 0; r < 2; r++) {
            int q = tid + r * 256;
            int m = q >> 3, kq = q & 7;
            float4 vx = *(const float4*)(x + (size_t)(m0 + m) * D_DIM + k0 + kq * 4);
            *(float4*)&sA[m * ASTRIDE + kq * 4] = vx;
            float4 vw = *(const float4*)(wg + (size_t)m * D_DIM + k0 + kq * 4);
            *(float4*)&sB[m * ASTRIDE + kq * 4] = vw;
        }
        __syncthreads();

        const size_t ziter = zblock + (size_t)it * 4096 + tid;
#pragma unroll
        for (int kk8 = 0; kk8 < 8; kk8++) {
            float4 a4[4], b4[4];
#pragma unroll
            for (int i = 0; i < 4; i++)
                a4[i] = *(const float4*)&sA[(ty + 16 * i) * ASTRIDE + kk8 * 4];
#pragma unroll
            for (int j = 0; j < 4; j++)
                b4[j] = *(const float4*)&sB[(tx + 16 * j) * ASTRIDE + kk8 * 4];
            // two interleaved zero stores (fire-and-forget, drain during FMA)
            __stcs(&out4[ziter + kk8 * 512], z4);
            __stcs(&out4[ziter + kk8 * 512 + 256], z4);
#pragma unroll
            for (int i = 0; i < 4; i++) {
                const float2* ap = (const float2*)&a4[i];
#pragma unroll
                for (int j = 0; j < 4; j++) {
                    const float2* bp = (const float2*)&b4[j];
                    ffma2(acc[i][j], ap[0], bp[0]);
                    ffma2(acc[i][j], ap[1], bp[1]);
                }
            }
        }
    }
    __syncthreads();

    float* logits = sm;   // [64][65]
#pragma unroll
    for (int i = 0; i < 4; i++)
#pragma unroll
        for (int j = 0; j < 4; j++)
            logits[(ty + 16 * i) * 65 + (tx + 16 * j)] = acc[i][j].x + acc[i][j].y;
    __syncthreads();

    if (tid < 64) {
        const float* row = &logits[tid * 65];
        float mx = row[0];
        int am = 0;
#pragma unroll 8
        for (int e = 1; e < 64; e++) {
            float v = row[e];
            if (v > mx) { mx = v; am = e; }
        }
        float sum = 0.f;
#pragma unroll 8
        for (int e = 0; e < 64; e++) sum += expf(row[e] - mx);
        float gate = 1.0f / sum;
        g_gate[m0 + tid] = gate;
        g_expert[m0 + tid] = am;
        smax[tid] = mx;
        sinv[tid] = gate;
    }
    __syncthreads();

    if (tid < 64) {
        float cs = 0.f;
#pragma unroll 8
        for (int t = 0; t < 64; t++)
            cs += expf(logits[t * 65 + tid] - smax[t]) * sinv[t];
        g_me_part[blockIdx.x * 64 + tid] = cs;
    }
}

// -------------------- scan + scatter + per-expert l_aux partial --------------
__global__ __launch_bounds__(256) void k_scan(float* __restrict__ out) {
    const int e = blockIdx.x;
    const int tid = threadIdx.x;
    __shared__ int ws[8];
    __shared__ int stot;
    __shared__ float wsum[4];
    int carry = 0;
    for (int itr = 0; itr < S_TOK / 256; itr++) {
        int s = itr * 256 + tid;
        int ind = (g_expert[s] == e);
        unsigned bal = __ballot_sync(0xffffffffu, ind);
        int lane = tid & 31, w = tid >> 5;
        int pre = __popc(bal & ((1u << lane) - 1u));
        if (lane == 0) ws[w] = __popc(bal);
        __syncthreads();
        if (tid == 0) {
            int a = 0;
#pragma unroll
            for (int i = 0; i < 8; i++) { int t = ws[i]; ws[i] = a; a += t; }
            stot = a;
        }
        __syncthreads();
        int loc = carry + ws[w] + pre;
        if (ind && loc < CAP) {
            size_t off = (size_t)s * (E_EXP * CAP) + e * CAP + loc;
            out[1 + off] = g_gate[s];
            out[1 + (size_t)SEC + off] = 1.0f;
        }
        carry += stot;
        __syncthreads();
    }
    // me_e = sum over 128 gate blocks of g_me_part[b][e]; parallel loads.
    float v = (tid < 128) ? g_me_part[tid * 64 + e] : 0.0f;
#pragma unroll
    for (int o = 16; o; o >>= 1) v += __shfl_down_sync(0xffffffffu, v, o);
    if ((tid & 31) == 0 && tid < 128) wsum[tid >> 5] = v;
    __syncthreads();
    if (tid == 0)
        g_vals[e] = (wsum[0] + wsum[1] + wsum[2] + wsum[3]) * (float)carry;
}

// -------------------- final l_aux + tail --------------------
__global__ void k_laux(float* __restrict__ out) {
    float v = (threadIdx.x < 64) ? g_vals[threadIdx.x] : 0.0f;
#pragma unroll
    for (int o = 16; o; o >>= 1) v += __shfl_down_sync(0xffffffffu, v, o);
    __shared__ float red[2];
    if ((threadIdx.x & 31) == 0) red[threadIdx.x >> 5] = v;
    __syncthreads();
    if (threadIdx.x == 0) {
        out[0] = (red[0] + red[1]) * (64.0f / (8192.0f * 8192.0f));
        out[LAST_F] = 0.0f;
    }
}

// -------------------- launch (strictly serial, single stream) ---------------
extern "C" void kernel_launch(void* const* d_in, const int* in_sizes, int n_in,
                              void* d_out, int out_size) {
    const float* x  = (const float*)d_in[0];
    const float* wg = (const float*)d_in[1];
    float* out = (float*)d_out;

    k_gatezero<<<S_TOK / 64, 256>>>(x, wg, (float4*)out);
    k_scan<<<E_EXP, 256>>>(out);
    k_laux<<<1, 64>>>(out);
}

// round 8
// speedup vs baseline: 1.5543x; 1.5543x over previous
#include <cuda_runtime.h>
#include <cuda_bf16.h>

// Problem constants
#define S_TOK 8192
#define D_DIM 2048
#define E_EXP 64
#define CAP   128
#define SEC   (S_TOK * E_EXP * CAP)   // 67108864
#define LAST_F 134217728              // tail float index; out_size = LAST_F+1
#define N4_ALL 33554432               // float4 covering floats [0, LAST_F)
#define NKS    4                      // split-K slices
#define KSLICE (D_DIM / NKS)          // 512
#define ZPB    (N4_ALL / 256)         // float4 zeroed per gate block = 131072

// -------------------- device scratch --------------------
__device__ float g_part[S_TOK * NKS * E_EXP];      // 8MB partial logits [s][ks][e]
__device__ float g_gate[S_TOK];
__device__ int   g_expert[S_TOK];
__device__ float g_me_part[64 * E_EXP];            // [soft-block][expert]
__device__ float g_vals[E_EXP];                    // me_e * cnt_e

// -------------------- packed fp32 FMA (FFMA2) --------------------
__device__ __forceinline__ void ffma2(float2& d, const float2& a, const float2& b) {
    unsigned long long dd = *(const unsigned long long*)&d;
    unsigned long long aa = *(const unsigned long long*)&a;
    unsigned long long bb = *(const unsigned long long*)&b;
    asm("fma.rn.f32x2 %0, %1, %2, %0;" : "+l"(dd) : "l"(aa), "l"(bb));
    d = *(float2*)&dd;
}

// -------------------- fused split-K GEMM + bulk zero ----------------
// Grid (4 ks, 64 mtile). BM=128 tokens, BN=64 experts, BK=32, k-slice 512.
// 256 threads = 16x16; thread tile 8 tokens x 4 experts.
// Each block zeroes 2MB of output interleaved (4 STG.128/thread/kk8 step).
#define ASTRIDE 36
__global__ __launch_bounds__(256, 2) void k_gatezero(const float* __restrict__ x,
                                                     const float* __restrict__ wg,
                                                     float4* __restrict__ out4) {
    __shared__ float sA[128 * ASTRIDE];   // 18KB
    __shared__ float sB[64 * ASTRIDE];    // 9KB

    const int tid = threadIdx.x;
    const int tx = tid & 15, ty = tid >> 4;
    const int ks = blockIdx.x;
    const int m0 = blockIdx.y * 128;
    const int kbase = ks * KSLICE;
    const size_t zb = ((size_t)blockIdx.y * 4 + ks) * ZPB;
    const float4 z4 = make_float4(0.f, 0.f, 0.f, 0.f);

    float2 acc[8][4];
#pragma unroll
    for (int i = 0; i < 8; i++)
#pragma unroll
        for (int j = 0; j < 4; j++) acc[i][j] = make_float2(0.f, 0.f);

    for (int it = 0; it < KSLICE / 32; it++) {
        const int k0 = kbase + it * 32;
        __syncthreads();
#pragma unroll
        for (int r = 0; r < 4; r++) {           // A tile: 1024 float4
            int q = tid + r * 256;
            int m = q >> 3, kq = q & 7;
            *(float4*)&sA[m * ASTRIDE + kq * 4] =
                *(const float4*)(x + (size_t)(m0 + m) * D_DIM + k0 + kq * 4);
        }
#pragma unroll
        for (int r = 0; r < 2; r++) {           // B tile: 512 float4
            int q = tid + r * 256;
            int m = q >> 3, kq = q & 7;
            *(float4*)&sB[m * ASTRIDE + kq * 4] =
                *(const float4*)(wg + (size_t)m * D_DIM + k0 + kq * 4);
        }
        __syncthreads();

        const size_t zit = zb + (size_t)it * 8192 + tid;
#pragma unroll
        for (int kk8 = 0; kk8 < 8; kk8++) {
            // 4 fire-and-forget zero stores per step (drain during FMAs)
            const size_t zs = zit + (size_t)kk8 * 1024;
            __stcs(&out4[zs], z4);
            __stcs(&out4[zs + 256], z4);
            __stcs(&out4[zs + 512], z4);
            __stcs(&out4[zs + 768], z4);

            float4 b4[4];
#pragma unroll
            for (int j = 0; j < 4; j++)
                b4[j] = *(const float4*)&sB[(tx + 16 * j) * ASTRIDE + kk8 * 4];
#pragma unroll
            for (int i = 0; i < 8; i++) {
                float4 a4 = *(const float4*)&sA[(ty + 16 * i) * ASTRIDE + kk8 * 4];
                const float2* ap = (const float2*)&a4;
#pragma unroll
                for (int j = 0; j < 4; j++) {
                    const float2* bp = (const float2*)&b4[j];
                    ffma2(acc[i][j], ap[0], bp[0]);
                    ffma2(acc[i][j], ap[1], bp[1]);
                }
            }
        }
    }

    // write partial logits: g_part[(m0+t)*4 + ks][e]
#pragma unroll
    for (int i = 0; i < 8; i++) {
        int t = m0 + ty + 16 * i;
        float* dst = g_part + ((size_t)t * NKS + ks) * E_EXP;
#pragma unroll
        for (int j = 0; j < 4; j++)
            dst[tx + 16 * j] = acc[i][j].x + acc[i][j].y;
    }
}

// -------------------- split-K reduce + softmax/argmax + me partials ----------
__global__ __launch_bounds__(128) void k_soft() {
    __shared__ float sg[128 * 65];     // 33.3KB: gates rows, padded
    const int tid = threadIdx.x;
    const int s = blockIdx.x * 128 + tid;

    float row[64];
    const float4* p = (const float4*)g_part + (size_t)s * 64;
#pragma unroll
    for (int e4 = 0; e4 < 16; e4++) {
        float4 v0 = p[e4], v1 = p[16 + e4], v2 = p[32 + e4], v3 = p[48 + e4];
        row[4 * e4 + 0] = v0.x + v1.x + v2.x + v3.x;
        row[4 * e4 + 1] = v0.y + v1.y + v2.y + v3.y;
        row[4 * e4 + 2] = v0.z + v1.z + v2.z + v3.z;
        row[4 * e4 + 3] = v0.w + v1.w + v2.w + v3.w;
    }

    float mx = row[0];
    int am = 0;
#pragma unroll
    for (int e = 1; e < 64; e++)
        if (row[e] > mx) { mx = row[e]; am = e; }
    float sum = 0.f;
#pragma unroll
    for (int e = 0; e < 64; e++) { row[e] = expf(row[e] - mx); sum += row[e]; }
    float gate = 1.0f / sum;
    g_gate[s] = gate;
    g_expert[s] = am;

    // gates row into padded smem for column sums (me)
#pragma unroll
    for (int e = 0; e < 64; e++) sg[tid * 65 + e] = row[e] * gate;
    __syncthreads();

    const int col = tid & 63, half = tid >> 6;
    float cs = 0.f;
#pragma unroll 16
    for (int t = 0; t < 64; t++)
        cs += sg[(half * 64 + t) * 65 + col];
    __syncthreads();
    sg[half * 64 + col] = cs;
    __syncthreads();
    if (tid < 64)
        g_me_part[blockIdx.x * 64 + tid] = sg[tid] + sg[64 + tid];
}

// -------------------- scan + scatter + per-expert l_aux partial --------------
__global__ __launch_bounds__(256) void k_scan(float* __restrict__ out) {
    const int e = blockIdx.x;
    const int tid = threadIdx.x;
    __shared__ int ws[8];
    __shared__ int stot;
    __shared__ float wsum[2];
    int carry = 0;
    for (int itr = 0; itr < S_TOK / 256; itr++) {
        int s = itr * 256 + tid;
        int ind = (g_expert[s] == e);
        unsigned bal = __ballot_sync(0xffffffffu, ind);
        int lane = tid & 31, w = tid >> 5;
        int pre = __popc(bal & ((1u << lane) - 1u));
        if (lane == 0) ws[w] = __popc(bal);
        __syncthreads();
        if (tid == 0) {
            int a = 0;
#pragma unroll
            for (int i = 0; i < 8; i++) { int t = ws[i]; ws[i] = a; a += t; }
            stot = a;
        }
        __syncthreads();
        int loc = carry + ws[w] + pre;
        if (ind && loc < CAP) {
            size_t off = (size_t)s * (E_EXP * CAP) + e * CAP + loc;
            out[1 + off] = g_gate[s];
            out[1 + (size_t)SEC + off] = 1.0f;
        }
        carry += stot;
        __syncthreads();
    }
    // me_e = sum over 64 soft blocks
    float v = (tid < 64) ? g_me_part[tid * 64 + e] : 0.0f;
#pragma unroll
    for (int o = 16; o; o >>= 1) v += __shfl_down_sync(0xffffffffu, v, o);
    if ((tid & 31) == 0 && tid < 64) wsum[tid >> 5] = v;
    __syncthreads();
    if (tid == 0)
        g_vals[e] = (wsum[0] + wsum[1]) * (float)carry;
}

// -------------------- final l_aux + tail --------------------
__global__ void k_laux(float* __restrict__ out) {
    float v = (threadIdx.x < 64) ? g_vals[threadIdx.x] : 0.0f;
#pragma unroll
    for (int o = 16; o; o >>= 1) v += __shfl_down_sync(0xffffffffu, v, o);
    __shared__ float red[2];
    if ((threadIdx.x & 31) == 0) red[threadIdx.x >> 5] = v;
    __syncthreads();
    if (threadIdx.x == 0) {
        out[0] = (red[0] + red[1]) * (64.0f / (8192.0f * 8192.0f));
        out[LAST_F] = 0.0f;
    }
}

// -------------------- launch (strictly serial, single stream) ---------------
extern "C" void kernel_launch(void* const* d_in, const int* in_sizes, int n_in,
                              void* d_out, int out_size) {
    const float* x  = (const float*)d_in[0];
    const float* wg = (const float*)d_in[1];
    float* out = (float*)d_out;

    k_gatezero<<<dim3(NKS, 64), 256>>>(x, wg, (float4*)out);
    k_soft<<<64, 128>>>();
    k_scan<<<E_EXP, 256>>>(out);
    k_laux<<<1, 64>>>(out);
}

// round 9
// speedup vs baseline: 1.6804x; 1.0811x over previous
#include <cuda_runtime.h>
#include <cuda_bf16.h>

// Problem constants
#define S_TOK 8192
#define D_DIM 2048
#define E_EXP 64
#define CAP   128
#define SEC   (S_TOK * E_EXP * CAP)   // 67108864
#define LAST_F 134217728              // tail float index; out_size = LAST_F+1
#define N4_ALL 33554432               // float4 covering floats [0, LAST_F)
#define NKS    4                      // split-K slices
#define KSLICE (D_DIM / NKS)          // 512
#define ZPB    (N4_ALL / 256)         // float4 zeroed per gate block = 131072
#define ASTRIDE 36
#define SMEM_BYTES (2 * (128 + 64) * ASTRIDE * 4)   // 55296

// -------------------- device scratch --------------------
__device__ float g_part[S_TOK * NKS * E_EXP];      // 8MB partial logits [s][ks][e]
__device__ float g_gate[S_TOK];
__device__ int   g_expert[S_TOK];
__device__ float g_me_part[64 * E_EXP];            // [soft-block][expert]
__device__ float g_vals[E_EXP];                    // me_e * cnt_e
__device__ int   g_ctr;                            // scan completion counter

// -------------------- packed fp32 FMA (FFMA2) --------------------
__device__ __forceinline__ void ffma2(float2& d, const float2& a, const float2& b) {
    unsigned long long dd = *(const unsigned long long*)&d;
    unsigned long long aa = *(const unsigned long long*)&a;
    unsigned long long bb = *(const unsigned long long*)&b;
    asm("fma.rn.f32x2 %0, %1, %2, %0;" : "+l"(dd) : "l"(aa), "l"(bb));
    d = *(float2*)&dd;
}

// -------------------- fused split-K GEMM + bulk zero, double-buffered --------
// Grid (4 ks, 64 mtile). BM=128, BN=64, BK=32, k-slice 512. 256 thr = 16x16,
// thread tile 8x4. Double-buffered SMEM: one __syncthreads per k-tile, LDG of
// tile it+1 overlapped with compute of tile it. Each block zeroes 2MB of the
// output (4 STG.128 per thread per kk8 step), draining during FMA issue.
__global__ __launch_bounds__(256, 2) void k_gatezero(const float* __restrict__ x,
                                                     const float* __restrict__ wg,
                                                     float4* __restrict__ out4) {
    extern __shared__ float smem[];
    float* sA = smem;                       // [2][128*ASTRIDE]
    float* sB = smem + 2 * 128 * ASTRIDE;   // [2][64*ASTRIDE]

    const int tid = threadIdx.x;
    const int tx = tid & 15, ty = tid >> 4;
    const int ks = blockIdx.x;
    const int m0 = blockIdx.y * 128;
    const int kbase = ks * KSLICE;
    const size_t zb = ((size_t)blockIdx.y * 4 + ks) * ZPB;
    const float4 z4 = make_float4(0.f, 0.f, 0.f, 0.f);

    // per-thread LDG targets (fixed across iterations except k offset)
    const int mA = tid >> 3, kqA = tid & 7;          // + r*32 rows
    float4 pa[4], pb[2];

    // prologue: tile 0
#pragma unroll
    for (int r = 0; r < 4; r++)
        pa[r] = *(const float4*)(x + (size_t)(m0 + mA + r * 32) * D_DIM + kbase + kqA * 4);
#pragma unroll
    for (int r = 0; r < 2; r++)
        pb[r] = *(const float4*)(wg + (size_t)(mA + r * 32) * D_DIM + kbase + kqA * 4);
#pragma unroll
    for (int r = 0; r < 4; r++)
        *(float4*)&sA[(mA + r * 32) * ASTRIDE + kqA * 4] = pa[r];
#pragma unroll
    for (int r = 0; r < 2; r++)
        *(float4*)&sB[(mA + r * 32) * ASTRIDE + kqA * 4] = pb[r];
    __syncthreads();

    float2 acc[8][4];
#pragma unroll
    for (int i = 0; i < 8; i++)
#pragma unroll
        for (int j = 0; j < 4; j++) acc[i][j] = make_float2(0.f, 0.f);

    for (int it = 0; it < KSLICE / 32; it++) {
        const int buf = it & 1;
        float* cA = sA + buf * 128 * ASTRIDE;
        float* cB = sB + buf * 64 * ASTRIDE;

        // prefetch next tile into registers (latency hidden by compute below)
        if (it < KSLICE / 32 - 1) {
            const int kn = kbase + (it + 1) * 32;
#pragma unroll
            for (int r = 0; r < 4; r++)
                pa[r] = *(const float4*)(x + (size_t)(m0 + mA + r * 32) * D_DIM + kn + kqA * 4);
#pragma unroll
            for (int r = 0; r < 2; r++)
                pb[r] = *(const float4*)(wg + (size_t)(mA + r * 32) * D_DIM + kn + kqA * 4);
        }

        const size_t zit = zb + (size_t)it * 8192 + tid;
#pragma unroll
        for (int kk8 = 0; kk8 < 8; kk8++) {
            // fire-and-forget zero stores (drain during FMAs)
            const size_t zs = zit + (size_t)kk8 * 1024;
            __stcs(&out4[zs], z4);
            __stcs(&out4[zs + 256], z4);
            __stcs(&out4[zs + 512], z4);
            __stcs(&out4[zs + 768], z4);

            float4 b4[4];
#pragma unroll
            for (int j = 0; j < 4; j++)
                b4[j] = *(const float4*)&cB[(tx + 16 * j) * ASTRIDE + kk8 * 4];
#pragma unroll
            for (int i = 0; i < 8; i++) {
                float4 a4 = *(const float4*)&cA[(ty + 16 * i) * ASTRIDE + kk8 * 4];
                const float2* ap = (const float2*)&a4;
#pragma unroll
                for (int j = 0; j < 4; j++) {
                    const float2* bp = (const float2*)&b4[j];
                    ffma2(acc[i][j], ap[0], bp[0]);
                    ffma2(acc[i][j], ap[1], bp[1]);
                }
            }
        }

        if (it < KSLICE / 32 - 1) {
            float* nA = sA + (buf ^ 1) * 128 * ASTRIDE;
            float* nB = sB + (buf ^ 1) * 64 * ASTRIDE;
#pragma unroll
            for (int r = 0; r < 4; r++)
                *(float4*)&nA[(mA + r * 32) * ASTRIDE + kqA * 4] = pa[r];
#pragma unroll
            for (int r = 0; r < 2; r++)
                *(float4*)&nB[(mA + r * 32) * ASTRIDE + kqA * 4] = pb[r];
        }
        __syncthreads();
    }

    // write partial logits: g_part[(m0+t)*4 + ks][e]
#pragma unroll
    for (int i = 0; i < 8; i++) {
        int t = m0 + ty + 16 * i;
        float* dst = g_part + ((size_t)t * NKS + ks) * E_EXP;
#pragma unroll
        for (int j = 0; j < 4; j++)
            dst[tx + 16 * j] = acc[i][j].x + acc[i][j].y;
    }
}

// -------------------- split-K reduce + softmax/argmax + me partials ----------
__global__ __launch_bounds__(128) void k_soft(float* __restrict__ out) {
    __shared__ float sg[128 * 65];     // 33.3KB: gates rows, padded
    const int tid = threadIdx.x;
    const int s = blockIdx.x * 128 + tid;

    // zero the tail element BEFORE k_scan may scatter into it (fixes race)
    if (blockIdx.x == 0 && tid == 0) out[LAST_F] = 0.0f;

    float row[64];
    const float4* p = (const float4*)g_part + (size_t)s * 64;
#pragma unroll
    for (int e4 = 0; e4 < 16; e4++) {
        float4 v0 = p[e4], v1 = p[16 + e4], v2 = p[32 + e4], v3 = p[48 + e4];
        row[4 * e4 + 0] = v0.x + v1.x + v2.x + v3.x;
        row[4 * e4 + 1] = v0.y + v1.y + v2.y + v3.y;
        row[4 * e4 + 2] = v0.z + v1.z + v2.z + v3.z;
        row[4 * e4 + 3] = v0.w + v1.w + v2.w + v3.w;
    }

    float mx = row[0];
    int am = 0;
#pragma unroll
    for (int e = 1; e < 64; e++)
        if (row[e] > mx) { mx = row[e]; am = e; }
    float sum = 0.f;
#pragma unroll
    for (int e = 0; e < 64; e++) { row[e] = expf(row[e] - mx); sum += row[e]; }
    float gate = 1.0f / sum;
    g_gate[s] = gate;
    g_expert[s] = am;

#pragma unroll
    for (int e = 0; e < 64; e++) sg[tid * 65 + e] = row[e] * gate;
    __syncthreads();

    const int col = tid & 63, half = tid >> 6;
    float cs = 0.f;
#pragma unroll 16
    for (int t = 0; t < 64; t++)
        cs += sg[(half * 64 + t) * 65 + col];
    __syncthreads();
    sg[half * 64 + col] = cs;
    __syncthreads();
    if (tid < 64)
        g_me_part[blockIdx.x * 64 + tid] = sg[tid] + sg[64 + tid];
}

// -------------------- scan + scatter + l_aux (last-block reduction) ----------
__global__ __launch_bounds__(256) void k_scan(float* __restrict__ out) {
    const int e = blockIdx.x;
    const int tid = threadIdx.x;
    __shared__ int ws[8];
    __shared__ int stot;
    __shared__ float wsum[2];
    __shared__ int lastflag;
    int carry = 0;
    for (int itr = 0; itr < S_TOK / 256; itr++) {
        int s = itr * 256 + tid;
        int ind = (g_expert[s] == e);
        unsigned bal = __ballot_sync(0xffffffffu, ind);
        int lane = tid & 31, w = tid >> 5;
        int pre = __popc(bal & ((1u << lane) - 1u));
        if (lane == 0) ws[w] = __popc(bal);
        __syncthreads();
        if (tid == 0) {
            int a = 0;
#pragma unroll
            for (int i = 0; i < 8; i++) { int t = ws[i]; ws[i] = a; a += t; }
            stot = a;
        }
        __syncthreads();
        int loc = carry + ws[w] + pre;
        if (ind && loc < CAP) {
            size_t off = (size_t)s * (E_EXP * CAP) + e * CAP + loc;
            out[1 + off] = g_gate[s];
            out[1 + (size_t)SEC + off] = 1.0f;
        }
        carry += stot;
        __syncthreads();
    }
    // me_e = sum over 64 soft blocks
    float v = (tid < 64) ? g_me_part[tid * 64 + e] : 0.0f;
#pragma unroll
    for (int o = 16; o; o >>= 1) v += __shfl_down_sync(0xffffffffu, v, o);
    if ((tid & 31) == 0 && tid < 64) wsum[tid >> 5] = v;
    __syncthreads();
    if (tid == 0) {
        g_vals[e] = (wsum[0] + wsum[1]) * (float)carry;
        __threadfence();
        int done = atomicAdd(&g_ctr, 1);
        lastflag = (done == E_EXP - 1);
    }
    __syncthreads();
    if (lastflag) {
        float lv = (tid < 64) ? ((volatile float*)g_vals)[tid] : 0.0f;
#pragma unroll
        for (int o = 16; o; o >>= 1) lv += __shfl_down_sync(0xffffffffu, lv, o);
        __shared__ float red[2];
        if ((tid & 31) == 0 && tid < 64) red[tid >> 5] = lv;
        __syncthreads();
        if (tid == 0) {
            out[0] = (red[0] + red[1]) * (64.0f / (8192.0f * 8192.0f));
            g_ctr = 0;   // reset for deterministic graph replay
        }
    }
}

// -------------------- launch (strictly serial, single stream) ---------------
extern "C" void kernel_launch(void* const* d_in, const int* in_sizes, int n_in,
                              void* d_out, int out_size) {
    const float* x  = (const float*)d_in[0];
    const float* wg = (const float*)d_in[1];
    float* out = (float*)d_out;

    static bool attr_set = false;
    if (!attr_set) {
        cudaFuncSetAttribute(k_gatezero,
                             cudaFuncAttributeMaxDynamicSharedMemorySize,
                             SMEM_BYTES);
        attr_set = true;
    }

    k_gatezero<<<dim3(NKS, 64), 256, SMEM_BYTES>>>(x, wg, (float4*)out);
    k_soft<<<64, 128>>>(out);
    k_scan<<<E_EXP, 256>>>(out);
}

// round 10
// speedup vs baseline: 1.7213x; 1.0243x over previous
#include <cuda_runtime.h>
#include <cuda_bf16.h>

// Problem constants
#define S_TOK 8192
#define D_DIM 2048
#define E_EXP 64
#define CAP   128
#define SEC   (S_TOK * E_EXP * CAP)   // 67108864
#define LAST_F 134217728              // tail float index; out_size = LAST_F+1
#define N4_ALL 33554432               // float4 covering floats [0, LAST_F)
#define NKS    4                      // split-K slices
#define KSLICE (D_DIM / NKS)          // 512
#define ZBYTES_PER_BLOCK 2097152u     // 2MB zeroed per block (256 blocks)
#define ZCHUNK 16384u                 // bulk-store chunk (16KB)
#define ASTRIDE 36

// dynamic SMEM: [zero buf 4096 floats][sA 2*128*36][sB 2*64*36] = 17920 floats
#define ZBUF_FLOATS 4096
#define SA_OFF ZBUF_FLOATS
#define SB_OFF (ZBUF_FLOATS + 2 * 128 * ASTRIDE)
#define SMEM_FLOATS (ZBUF_FLOATS + 2 * 128 * ASTRIDE + 2 * 64 * ASTRIDE)
#define SMEM_BYTES (SMEM_FLOATS * 4)  // 71680

// -------------------- device scratch --------------------
__device__ float g_part[S_TOK * NKS * E_EXP];      // 8MB partial logits [s][ks][e]
__device__ float g_gate[S_TOK];
__device__ int   g_expert[S_TOK];
__device__ float g_me_part[64 * E_EXP];            // [mtile][expert]
__device__ float g_vals[E_EXP];                    // me_e * cnt_e
__device__ int   g_ctr;                            // scan completion counter
__device__ int   g_tilectr[64];                    // per-mtile ks completion

// -------------------- packed fp32 FMA (FFMA2) --------------------
__device__ __forceinline__ void ffma2(float2& d, const float2& a, const float2& b) {
    unsigned long long dd = *(const unsigned long long*)&d;
    unsigned long long aa = *(const unsigned long long*)&a;
    unsigned long long bb = *(const unsigned long long*)&b;
    asm("fma.rn.f32x2 %0, %1, %2, %0;" : "+l"(dd) : "l"(aa), "l"(bb));
    d = *(float2*)&dd;
}

__device__ __forceinline__ unsigned smem_u32(const void* p) {
    unsigned a;
    asm("{ .reg .u64 t; cvta.to.shared.u64 t, %1; cvt.u32.u64 %0, t; }"
        : "=r"(a) : "l"(p));
    return a;
}

// -------------------- fused split-K GEMM + TMA bulk zero + softmax epilogue --
// Grid (4 ks, 64 mtile). BM=128, BN=64, BK=32. 256 thr = 16x16, tile 8x4.
// Zeros go out via cp.async.bulk (TMA engine): zero issue cost on the LSU,
// drains at LTS cap concurrently with FMA/LDS. Last ks-block per mtile
// reduces partials -> softmax/argmax/me (fused, overlapped with other zeros).
__global__ __launch_bounds__(256, 2) void k_gatezero(const float* __restrict__ x,
                                                     const float* __restrict__ wg,
                                                     float* __restrict__ out) {
    extern __shared__ float smem[];
    float* zbuf = smem;
    float* sA = smem + SA_OFF;
    float* sB = smem + SB_OFF;

    const int tid = threadIdx.x;
    const int tx = tid & 15, ty = tid >> 4;
    const int ks = blockIdx.x;
    const int mtile = blockIdx.y;
    const int m0 = mtile * 128;
    const int kbase = ks * KSLICE;
    char* zdst = (char*)out + (size_t)(mtile * 4 + ks) * ZBYTES_PER_BLOCK;

    // zero the TMA staging buffer (stays zero for the whole kernel)
#pragma unroll
    for (int r = 0; r < 4; r++)
        *(float4*)&zbuf[(tid + r * 256) * 4] = make_float4(0.f, 0.f, 0.f, 0.f);

    // prologue loads: tile 0
    const int mA = tid >> 3, kqA = tid & 7;
    float4 pa[4], pb[2];
#pragma unroll
    for (int r = 0; r < 4; r++)
        pa[r] = *(const float4*)(x + (size_t)(m0 + mA + r * 32) * D_DIM + kbase + kqA * 4);
#pragma unroll
    for (int r = 0; r < 2; r++)
        pb[r] = *(const float4*)(wg + (size_t)(mA + r * 32) * D_DIM + kbase + kqA * 4);
#pragma unroll
    for (int r = 0; r < 4; r++)
        *(float4*)&sA[(mA + r * 32) * ASTRIDE + kqA * 4] = pa[r];
#pragma unroll
    for (int r = 0; r < 2; r++)
        *(float4*)&sB[(mA + r * 32) * ASTRIDE + kqA * 4] = pb[r];
    if (mtile == 0 && ks == 0 && tid == 255) out[LAST_F] = 0.0f;
    __syncthreads();

    const unsigned zsrc = smem_u32(zbuf);
    if (tid == 0) asm volatile("fence.proxy.async;" ::: "memory");

    float2 acc[8][4];
#pragma unroll
    for (int i = 0; i < 8; i++)
#pragma unroll
        for (int j = 0; j < 4; j++) acc[i][j] = make_float2(0.f, 0.f);

    for (int it = 0; it < KSLICE / 32; it++) {
        const int buf = it & 1;
        float* cA = sA + buf * 128 * ASTRIDE;
        float* cB = sB + buf * 64 * ASTRIDE;

        // 8 TMA bulk zero-stores per iteration (128 total = 2MB)
        if (tid == 0) {
#pragma unroll
            for (int c = 0; c < 8; c++) {
                char* g = zdst + (size_t)(it * 8 + c) * ZCHUNK;
                asm volatile(
                    "cp.async.bulk.global.shared::cta.bulk_group [%0], [%1], %2;"
                    :: "l"(g), "r"(zsrc), "n"(ZCHUNK) : "memory");
            }
        }

        // prefetch next tile
        if (it < KSLICE / 32 - 1) {
            const int kn = kbase + (it + 1) * 32;
#pragma unroll
            for (int r = 0; r < 4; r++)
                pa[r] = *(const float4*)(x + (size_t)(m0 + mA + r * 32) * D_DIM + kn + kqA * 4);
#pragma unroll
            for (int r = 0; r < 2; r++)
                pb[r] = *(const float4*)(wg + (size_t)(mA + r * 32) * D_DIM + kn + kqA * 4);
        }

#pragma unroll
        for (int kk8 = 0; kk8 < 8; kk8++) {
            float4 b4[4];
#pragma unroll
            for (int j = 0; j < 4; j++)
                b4[j] = *(const float4*)&cB[(tx + 16 * j) * ASTRIDE + kk8 * 4];
#pragma unroll
            for (int i = 0; i < 8; i++) {
                float4 a4 = *(const float4*)&cA[(ty + 16 * i) * ASTRIDE + kk8 * 4];
                const float2* ap = (const float2*)&a4;
#pragma unroll
                for (int j = 0; j < 4; j++) {
                    const float2* bp = (const float2*)&b4[j];
                    ffma2(acc[i][j], ap[0], bp[0]);
                    ffma2(acc[i][j], ap[1], bp[1]);
                }
            }
        }

        if (it < KSLICE / 32 - 1) {
            float* nA = sA + (buf ^ 1) * 128 * ASTRIDE;
            float* nB = sB + (buf ^ 1) * 64 * ASTRIDE;
#pragma unroll
            for (int r = 0; r < 4; r++)
                *(float4*)&nA[(mA + r * 32) * ASTRIDE + kqA * 4] = pa[r];
#pragma unroll
            for (int r = 0; r < 2; r++)
                *(float4*)&nB[(mA + r * 32) * ASTRIDE + kqA * 4] = pb[r];
        }
        __syncthreads();
    }

    if (tid == 0) asm volatile("cp.async.bulk.commit_group;" ::: "memory");

    // write partial logits: g_part[(m0+t)*4 + ks][e]
#pragma unroll
    for (int i = 0; i < 8; i++) {
        int t = m0 + ty + 16 * i;
        float* dst = g_part + ((size_t)t * NKS + ks) * E_EXP;
#pragma unroll
        for (int j = 0; j < 4; j++)
            dst[tx + 16 * j] = acc[i][j].x + acc[i][j].y;
    }

    // ---- fused softmax epilogue: last ks-block of this mtile ----
    __shared__ int s_last;
    if (tid == 0) {
        __threadfence();
        int done = atomicAdd(&g_tilectr[mtile], 1);
        s_last = (done == NKS - 1);
        if (s_last) g_tilectr[mtile] = 0;   // reset for graph replay
    }
    __syncthreads();
    if (s_last) {
        float* sg = smem + ZBUF_FLOATS;          // 128*65 floats (over sA/sB)
        float* sq = sg + 128 * 65;               // 4*64 partial col sums
        if (tid < 128) {
            int t = m0 + tid;
            const float4* p = (const float4*)g_part + (size_t)t * 64;
            float row[64];
#pragma unroll
            for (int e4 = 0; e4 < 16; e4++) {
                float4 v0 = __ldcg(p + e4);
                float4 v1 = __ldcg(p + 16 + e4);
                float4 v2 = __ldcg(p + 32 + e4);
                float4 v3 = __ldcg(p + 48 + e4);
                row[4 * e4 + 0] = v0.x + v1.x + v2.x + v3.x;
                row[4 * e4 + 1] = v0.y + v1.y + v2.y + v3.y;
                row[4 * e4 + 2] = v0.z + v1.z + v2.z + v3.z;
                row[4 * e4 + 3] = v0.w + v1.w + v2.w + v3.w;
            }
            float mx = row[0];
            int am = 0;
#pragma unroll
            for (int e = 1; e < 64; e++)
                if (row[e] > mx) { mx = row[e]; am = e; }
            float sum = 0.f;
#pragma unroll
            for (int e = 0; e < 64; e++) { row[e] = expf(row[e] - mx); sum += row[e]; }
            float gate = 1.0f / sum;
            g_gate[t] = gate;
            g_expert[t] = am;
#pragma unroll
            for (int e = 0; e < 64; e++) sg[tid * 65 + e] = row[e] * gate;
        }
        __syncthreads();
        {
            int col = tid & 63, q = tid >> 6;
            float cs = 0.f;
#pragma unroll 8
            for (int r = 0; r < 32; r++)
                cs += sg[(q * 32 + r) * 65 + col];
            sq[q * 64 + col] = cs;
        }
        __syncthreads();
        if (tid < 64)
            g_me_part[mtile * 64 + tid] = sq[tid] + sq[64 + tid] + sq[128 + tid] + sq[192 + tid];
    }

    // ensure all TMA zero-stores complete before kernel exit
    if (tid == 0)
        asm volatile("cp.async.bulk.wait_group 0;" ::: "memory");
}

// -------------------- scan + scatter + l_aux (last-block reduction) ----------
__global__ __launch_bounds__(256) void k_scan(float* __restrict__ out) {
    const int e = blockIdx.x;
    const int tid = threadIdx.x;
    __shared__ int ws[8];
    __shared__ int stot;
    __shared__ float wsum[2];
    __shared__ int lastflag;
    int carry = 0;
    for (int itr = 0; itr < S_TOK / 256; itr++) {
        int s = itr * 256 + tid;
        int ind = (g_expert[s] == e);
        unsigned bal = __ballot_sync(0xffffffffu, ind);
        int lane = tid & 31, w = tid >> 5;
        int pre = __popc(bal & ((1u << lane) - 1u));
        if (lane == 0) ws[w] = __popc(bal);
        __syncthreads();
        if (tid == 0) {
            int a = 0;
#pragma unroll
            for (int i = 0; i < 8; i++) { int t = ws[i]; ws[i] = a; a += t; }
            stot = a;
        }
        __syncthreads();
        int loc = carry + ws[w] + pre;
        if (ind && loc < CAP) {
            size_t off = (size_t)s * (E_EXP * CAP) + e * CAP + loc;
            out[1 + off] = g_gate[s];
            out[1 + (size_t)SEC + off] = 1.0f;
        }
        carry += stot;
        __syncthreads();
    }
    // me_e = sum over 64 mtiles
    float v = (tid < 64) ? g_me_part[tid * 64 + e] : 0.0f;
#pragma unroll
    for (int o = 16; o; o >>= 1) v += __shfl_down_sync(0xffffffffu, v, o);
    if ((tid & 31) == 0 && tid < 64) wsum[tid >> 5] = v;
    __syncthreads();
    if (tid == 0) {
        g_vals[e] = (wsum[0] + wsum[1]) * (float)carry;
        __threadfence();
        int done = atomicAdd(&g_ctr, 1);
        lastflag = (done == E_EXP - 1);
    }
    __syncthreads();
    if (lastflag) {
        float lv = (tid < 64) ? ((volatile float*)g_vals)[tid] : 0.0f;
#pragma unroll
        for (int o = 16; o; o >>= 1) lv += __shfl_down_sync(0xffffffffu, lv, o);
        __shared__ float red[2];
        if ((tid & 31) == 0 && tid < 64) red[tid >> 5] = lv;
        __syncthreads();
        if (tid == 0) {
            out[0] = (red[0] + red[1]) * (64.0f / (8192.0f * 8192.0f));
            g_ctr = 0;   // reset for deterministic graph replay
        }
    }
}

// -------------------- launch (strictly serial, single stream) ---------------
extern "C" void kernel_launch(void* const* d_in, const int* in_sizes, int n_in,
                              void* d_out, int out_size) {
    const float* x  = (const float*)d_in[0];
    const float* wg = (const float*)d_in[1];
    float* out = (float*)d_out;

    static bool attr_set = false;
    if (!attr_set) {
        cudaFuncSetAttribute(k_gatezero,
                             cudaFuncAttributeMaxDynamicSharedMemorySize,
                             SMEM_BYTES);
        attr_set = true;
    }

    k_gatezero<<<dim3(NKS, 64), 256, SMEM_BYTES>>>(x, wg, out);
    k_scan<<<E_EXP, 256>>>(out);
}

// round 11
// speedup vs baseline: 1.8592x; 1.0801x over previous
#include <cuda_runtime.h>
#include <cuda_bf16.h>

// Problem constants
#define S_TOK 8192
#define D_DIM 2048
#define E_EXP 64
#define CAP   128
#define SEC   (S_TOK * E_EXP * CAP)   // 67108864
#define LAST_F 134217728              // tail float index; out_size = LAST_F+1
#define NKS    4                      // split-K slices
#define KSLICE (D_DIM / NKS)          // 512
#define ZBYTES_PER_BLOCK 2097152u     // 2MB zeroed per block (256 blocks)
#define ZCHUNK 16384u                 // bulk-store chunk (16KB)
#define ASTRIDE 36

// dynamic SMEM: [zero buf 4096 floats][sA 2*128*36][sB 2*64*36]
#define ZBUF_FLOATS 4096
#define SA_OFF ZBUF_FLOATS
#define SB_OFF (ZBUF_FLOATS + 2 * 128 * ASTRIDE)
#define SMEM_FLOATS (ZBUF_FLOATS + 2 * 128 * ASTRIDE + 2 * 64 * ASTRIDE)
#define SMEM_BYTES (SMEM_FLOATS * 4)  // 71680

// -------------------- device scratch --------------------
__device__ float g_part[S_TOK * NKS * E_EXP];      // 8MB partial logits [s][ks][e]
__device__ float g_gate[S_TOK];
__device__ int   g_expert[S_TOK];
__device__ float g_me_part[64 * E_EXP];            // [mtile][expert]
__device__ float g_vals[E_EXP];                    // me_e * cnt_e
__device__ int   g_ctr;                            // scan completion counter
__device__ int   g_tilectr[64];                    // per-mtile ks completion

// -------------------- packed fp32 FMA (FFMA2) --------------------
__device__ __forceinline__ void ffma2(float2& d, const float2& a, const float2& b) {
    unsigned long long dd = *(const unsigned long long*)&d;
    unsigned long long aa = *(const unsigned long long*)&a;
    unsigned long long bb = *(const unsigned long long*)&b;
    asm("fma.rn.f32x2 %0, %1, %2, %0;" : "+l"(dd) : "l"(aa), "l"(bb));
    d = *(float2*)&dd;
}

__device__ __forceinline__ unsigned smem_u32(const void* p) {
    unsigned a;
    asm("{ .reg .u64 t; cvta.to.shared.u64 t, %1; cvt.u32.u64 %0, t; }"
        : "=r"(a) : "l"(p));
    return a;
}

// -------------------- fused split-K GEMM + TMA bulk zero + softmax epilogue --
__global__ __launch_bounds__(256, 2) void k_gatezero(const float* __restrict__ x,
                                                     const float* __restrict__ wg,
                                                     float* __restrict__ out) {
    extern __shared__ float smem[];
    float* zbuf = smem;
    float* sA = smem + SA_OFF;
    float* sB = smem + SB_OFF;

    const int tid = threadIdx.x;
    const int tx = tid & 15, ty = tid >> 4;
    const int ks = blockIdx.x;
    const int mtile = blockIdx.y;
    const int m0 = mtile * 128;
    const int kbase = ks * KSLICE;
    char* zdst = (char*)out + (size_t)(mtile * 4 + ks) * ZBYTES_PER_BLOCK;

    // zero the TMA staging buffer (stays zero for the whole kernel)
#pragma unroll
    for (int r = 0; r < 4; r++)
        *(float4*)&zbuf[(tid + r * 256) * 4] = make_float4(0.f, 0.f, 0.f, 0.f);

    // prologue loads: tile 0
    const int mA = tid >> 3, kqA = tid & 7;
    float4 pa[4], pb[2];
#pragma unroll
    for (int r = 0; r < 4; r++)
        pa[r] = *(const float4*)(x + (size_t)(m0 + mA + r * 32) * D_DIM + kbase + kqA * 4);
#pragma unroll
    for (int r = 0; r < 2; r++)
        pb[r] = *(const float4*)(wg + (size_t)(mA + r * 32) * D_DIM + kbase + kqA * 4);
#pragma unroll
    for (int r = 0; r < 4; r++)
        *(float4*)&sA[(mA + r * 32) * ASTRIDE + kqA * 4] = pa[r];
#pragma unroll
    for (int r = 0; r < 2; r++)
        *(float4*)&sB[(mA + r * 32) * ASTRIDE + kqA * 4] = pb[r];
    if (mtile == 0 && ks == 0 && tid == 255) out[LAST_F] = 0.0f;
    __syncthreads();

    const unsigned zsrc = smem_u32(zbuf);
    if (tid == 0) asm volatile("fence.proxy.async;" ::: "memory");

    float2 acc[8][4];
#pragma unroll
    for (int i = 0; i < 8; i++)
#pragma unroll
        for (int j = 0; j < 4; j++) acc[i][j] = make_float2(0.f, 0.f);

    for (int it = 0; it < KSLICE / 32; it++) {
        const int buf = it & 1;
        float* cA = sA + buf * 128 * ASTRIDE;
        float* cB = sB + buf * 64 * ASTRIDE;

        // 8 TMA bulk zero-stores per iteration (128 total = 2MB)
        if (tid == 0) {
#pragma unroll
            for (int c = 0; c < 8; c++) {
                char* g = zdst + (size_t)(it * 8 + c) * ZCHUNK;
                asm volatile(
                    "cp.async.bulk.global.shared::cta.bulk_group [%0], [%1], %2;"
                    :: "l"(g), "r"(zsrc), "n"(ZCHUNK) : "memory");
            }
        }

        // prefetch next tile
        if (it < KSLICE / 32 - 1) {
            const int kn = kbase + (it + 1) * 32;
#pragma unroll
            for (int r = 0; r < 4; r++)
                pa[r] = *(const float4*)(x + (size_t)(m0 + mA + r * 32) * D_DIM + kn + kqA * 4);
#pragma unroll
            for (int r = 0; r < 2; r++)
                pb[r] = *(const float4*)(wg + (size_t)(mA + r * 32) * D_DIM + kn + kqA * 4);
        }

#pragma unroll
        for (int kk8 = 0; kk8 < 8; kk8++) {
            float4 b4[4];
#pragma unroll
            for (int j = 0; j < 4; j++)
                b4[j] = *(const float4*)&cB[(tx + 16 * j) * ASTRIDE + kk8 * 4];
#pragma unroll
            for (int i = 0; i < 8; i++) {
                float4 a4 = *(const float4*)&cA[(ty + 16 * i) * ASTRIDE + kk8 * 4];
                const float2* ap = (const float2*)&a4;
#pragma unroll
                for (int j = 0; j < 4; j++) {
                    const float2* bp = (const float2*)&b4[j];
                    ffma2(acc[i][j], ap[0], bp[0]);
                    ffma2(acc[i][j], ap[1], bp[1]);
                }
            }
        }

        if (it < KSLICE / 32 - 1) {
            float* nA = sA + (buf ^ 1) * 128 * ASTRIDE;
            float* nB = sB + (buf ^ 1) * 64 * ASTRIDE;
#pragma unroll
            for (int r = 0; r < 4; r++)
                *(float4*)&nA[(mA + r * 32) * ASTRIDE + kqA * 4] = pa[r];
#pragma unroll
            for (int r = 0; r < 2; r++)
                *(float4*)&nB[(mA + r * 32) * ASTRIDE + kqA * 4] = pb[r];
        }
        __syncthreads();
    }

    if (tid == 0) asm volatile("cp.async.bulk.commit_group;" ::: "memory");

    // write partial logits: g_part[(m0+t)*4 + ks][e]
#pragma unroll
    for (int i = 0; i < 8; i++) {
        int t = m0 + ty + 16 * i;
        float* dst = g_part + ((size_t)t * NKS + ks) * E_EXP;
#pragma unroll
        for (int j = 0; j < 4; j++)
            dst[tx + 16 * j] = acc[i][j].x + acc[i][j].y;
    }

    // ---- fused softmax epilogue: last ks-block of this mtile ----
    __shared__ int s_last;
    if (tid == 0) {
        __threadfence();
        int done = atomicAdd(&g_tilectr[mtile], 1);
        s_last = (done == NKS - 1);
        if (s_last) g_tilectr[mtile] = 0;   // reset for graph replay
    }
    __syncthreads();
    if (s_last) {
        float* sg = smem + ZBUF_FLOATS;          // 128*65 floats (over sA/sB)
        float* sq = sg + 128 * 65;               // 4*64 partial col sums
        if (tid < 128) {
            int t = m0 + tid;
            const float4* p = (const float4*)g_part + (size_t)t * 64;
            float row[64];
#pragma unroll
            for (int e4 = 0; e4 < 16; e4++) {
                float4 v0 = __ldcg(p + e4);
                float4 v1 = __ldcg(p + 16 + e4);
                float4 v2 = __ldcg(p + 32 + e4);
                float4 v3 = __ldcg(p + 48 + e4);
                row[4 * e4 + 0] = v0.x + v1.x + v2.x + v3.x;
                row[4 * e4 + 1] = v0.y + v1.y + v2.y + v3.y;
                row[4 * e4 + 2] = v0.z + v1.z + v2.z + v3.z;
                row[4 * e4 + 3] = v0.w + v1.w + v2.w + v3.w;
            }
            float mx = row[0];
            int am = 0;
#pragma unroll
            for (int e = 1; e < 64; e++)
                if (row[e] > mx) { mx = row[e]; am = e; }
            float sum = 0.f;
#pragma unroll
            for (int e = 0; e < 64; e++) { row[e] = expf(row[e] - mx); sum += row[e]; }
            float gate = 1.0f / sum;
            g_gate[t] = gate;
            g_expert[t] = am;
#pragma unroll
            for (int e = 0; e < 64; e++) sg[tid * 65 + e] = row[e] * gate;
        }
        __syncthreads();
        {
            int col = tid & 63, q = tid >> 6;
            float cs = 0.f;
#pragma unroll 8
            for (int r = 0; r < 32; r++)
                cs += sg[(q * 32 + r) * 65 + col];
            sq[q * 64 + col] = cs;
        }
        __syncthreads();
        if (tid < 64)
            g_me_part[mtile * 64 + tid] = sq[tid] + sq[64 + tid] + sq[128 + tid] + sq[192 + tid];
    }

    // ensure all TMA zero-stores complete before kernel exit
    if (tid == 0)
        asm volatile("cp.async.bulk.wait_group 0;" ::: "memory");
}

// -------------------- scan + scatter + l_aux: single-pass per expert ---------
// One block per expert. Each thread owns 32 consecutive tokens (8 int4 LDGs,
// all in flight -> one latency round-trip), one block-wide exclusive scan,
// then serial in-order emission of positions. No iteration loop.
__global__ __launch_bounds__(256) void k_scan(float* __restrict__ out) {
    const int e = blockIdx.x;
    const int tid = threadIdx.x;
    const int lane = tid & 31, w = tid >> 5;
    __shared__ int wtot[8];
    __shared__ int s_total;
    __shared__ float wsum[2];
    __shared__ int lastflag;

    // load 32 expert ids (tokens tid*32 .. tid*32+31)
    int4 idv[8];
    const int4* ip = (const int4*)g_expert + (size_t)tid * 8;
#pragma unroll
    for (int r = 0; r < 8; r++) idv[r] = __ldg(ip + r);
    const int* ids = (const int*)idv;

    int cnt = 0;
#pragma unroll
    for (int k = 0; k < 32; k++) cnt += (ids[k] == e);

    // inclusive warp scan of cnt
    int inc = cnt;
#pragma unroll
    for (int o = 1; o < 32; o <<= 1) {
        int t = __shfl_up_sync(0xffffffffu, inc, o);
        if (lane >= o) inc += t;
    }
    if (lane == 31) wtot[w] = inc;
    __syncthreads();
    if (tid == 0) {
        int a = 0;
#pragma unroll
        for (int i = 0; i < 8; i++) { int t = wtot[i]; wtot[i] = a; a += t; }
        s_total = a;
    }
    __syncthreads();

    int base = wtot[w] + inc - cnt;    // exclusive prefix for this thread
    if (cnt > 0 && base < CAP) {
        const int s0 = tid * 32;
#pragma unroll
        for (int k = 0; k < 32; k++) {
            if (ids[k] == e) {
                if (base < CAP) {
                    int s = s0 + k;
                    size_t off = (size_t)s * (E_EXP * CAP) + e * CAP + base;
                    out[1 + off] = g_gate[s];
                    out[1 + (size_t)SEC + off] = 1.0f;
                }
                base++;
            }
        }
    }

    // me_e = sum over 64 mtiles; then l_aux by the last block to finish
    float v = (tid < 64) ? g_me_part[tid * 64 + e] : 0.0f;
#pragma unroll
    for (int o = 16; o; o >>= 1) v += __shfl_down_sync(0xffffffffu, v, o);
    if ((tid & 31) == 0 && tid < 64) wsum[tid >> 5] = v;
    __syncthreads();
    if (tid == 0) {
        g_vals[e] = (wsum[0] + wsum[1]) * (float)s_total;
        __threadfence();
        int done = atomicAdd(&g_ctr, 1);
        lastflag = (done == E_EXP - 1);
    }
    __syncthreads();
    if (lastflag) {
        float lv = (tid < 64) ? ((volatile float*)g_vals)[tid] : 0.0f;
#pragma unroll
        for (int o = 16; o; o >>= 1) lv += __shfl_down_sync(0xffffffffu, lv, o);
        __shared__ float red[2];
        if ((tid & 31) == 0 && tid < 64) red[tid >> 5] = lv;
        __syncthreads();
        if (tid == 0) {
            out[0] = (red[0] + red[1]) * (64.0f / (8192.0f * 8192.0f));
            g_ctr = 0;   // reset for deterministic graph replay
        }
    }
}

// -------------------- launch (strictly serial, single stream) ---------------
extern "C" void kernel_launch(void* const* d_in, const int* in_sizes, int n_in,
                              void* d_out, int out_size) {
    const float* x  = (const float*)d_in[0];
    const float* wg = (const float*)d_in[1];
    float* out = (float*)d_out;

    static bool attr_set = false;
    if (!attr_set) {
        cudaFuncSetAttribute(k_gatezero,
                             cudaFuncAttributeMaxDynamicSharedMemorySize,
                             SMEM_BYTES);
        attr_set = true;
    }

    k_gatezero<<<dim3(NKS, 64), 256, SMEM_BYTES>>>(x, wg, out);
    k_scan<<<E_EXP, 256>>>(out);
}